// round 15
// baseline (speedup 1.0000x reference)
#include <cuda_runtime.h>
#include <cuda_fp16.h>
#include <cstdint>

#define BB 4
#define CC 256
#define NN 4096

#define SSPLIT 128.0f
#define INV_S  0.0078125f     // 1/128

// ---------------------------------------------------------------------------
// Scratch. 2-term operands: (h, m) with m = fp16(h + s*(v-h)), s=128.
// X = D1 + (D2-D1)/s reconstructs hi·hi + cross terms.
// ---------------------------------------------------------------------------
__device__ __half g_x1h[(size_t)BB * NN * CC];
__device__ __half g_x1m[(size_t)BB * NN * CC];
__device__ __half g_x2h[(size_t)BB * NN * CC];
__device__ __half g_x2m[(size_t)BB * NN * CC];
__device__ __half g_wh[3 * CC * CC];
__device__ __half g_wm[3 * CC * CC];
__device__ float  g_bias[3 * CC];
__device__ __half g_qh[(size_t)BB * NN * CC];
__device__ __half g_qm[(size_t)BB * NN * CC];
__device__ __half g_kh[(size_t)BB * NN * CC];
__device__ __half g_km[(size_t)BB * NN * CC];
__device__ __half g_vt[(size_t)BB * CC * NN];     // V^T fp16 [b][c][j]
__device__ __half g_p[(size_t)BB * NN * NN];      // P = exp(S - m_tile), fp16
__device__ float g_pm[(size_t)BB * NN * 32];      // per-(row, 128-col tile) max
__device__ float g_pl[(size_t)BB * NN * 32];
__device__ float g_m [BB * NN];
__device__ float g_li[BB * NN];

// ---------------------------------------------------------------------------
// PTX helpers
// ---------------------------------------------------------------------------
__device__ __forceinline__ uint32_t smem_u32(const void* p) {
    uint32_t a;
    asm("{ .reg .u64 t; cvta.to.shared.u64 t, %1; cvt.u32.u64 %0, t; }"
        : "=r"(a) : "l"(p));
    return a;
}

#define CP16(smem, gptr) \
    asm volatile("cp.async.ca.shared.global [%0], [%1], 16;" \
                 :: "r"(smem), "l"(gptr) : "memory")
#define CP_COMMIT() asm volatile("cp.async.commit_group;" ::: "memory")
#define CP_WAIT1()  asm volatile("cp.async.wait_group 1;" ::: "memory")
#define CP_WAIT0()  asm volatile("cp.async.wait_group 0;" ::: "memory")

#define LDSM4(r0, r1, r2, r3, addr) \
    asm volatile("ldmatrix.sync.aligned.m8n8.x4.shared.b16 {%0,%1,%2,%3}, [%4];" \
                 : "=r"(r0), "=r"(r1), "=r"(r2), "=r"(r3) : "r"(addr))

__device__ __forceinline__ void mma_f16(float* d, const uint32_t* a,
                                        uint32_t b0, uint32_t b1) {
    asm volatile(
        "mma.sync.aligned.m16n8k16.row.col.f32.f16.f16.f32 "
        "{%0,%1,%2,%3}, {%4,%5,%6,%7}, {%8,%9}, {%0,%1,%2,%3};"
        : "+f"(d[0]), "+f"(d[1]), "+f"(d[2]), "+f"(d[3])
        : "r"(a[0]), "r"(a[1]), "r"(a[2]), "r"(a[3]), "r"(b0), "r"(b1));
}

// k-chunk 64 fp16 = 128B/row, padded to 144B (conflict-free ldmatrix).
#define RSTR    144
// scores/proj stage: Ah(18432) Am(18432) Bh(18432) Bm(18432) = 73728, x3
#define A2M_D   18432
#define B2_OFF  36864
#define B2M_D   18432
#define STG2    73728
#define SMEM_2  (3 * STG2)     // 221184 (1 CTA/SM)
// pv stage: P(18432) V(36864) = 55296, x3
#define PB_OFF  18432
#define PSTG    55296
#define SMEM_P  (3 * PSTG)     // 165888

__device__ __forceinline__ float fast_exp(float x) {
    float y = fmaxf(x, -87.0f) * 1.4426950408889634f;
    float z = __fadd_rn(y, 12582912.0f);
    int   k = __float_as_int(z) - 0x4B400000;
    float f = __fsub_rn(y, __fsub_rn(z, 12582912.0f));
    float p =             1.33335581e-3f;
    p = fmaf(p, f, 9.61812910e-3f);
    p = fmaf(p, f, 5.55041087e-2f);
    p = fmaf(p, f, 2.40226507e-1f);
    p = fmaf(p, f, 6.93147181e-1f);
    p = fmaf(p, f, 1.0f);
    return __int_as_float(__float_as_int(p) + (k << 23));
}

__device__ __forceinline__ void f16_split2(float v, __half& h, __half& m) {
    h = __float2half_rn(v);
    float hf = __half2float(h);
    m = __float2half_rn(fmaf(SSPLIT, v - hf, hf));
}

// ---------------------------------------------------------------------------
// Prep kernels
// ---------------------------------------------------------------------------
__global__ void wsplit_kernel(const float* __restrict__ Wq,
                              const float* __restrict__ Wk,
                              const float* __restrict__ Wv)
{
    int t = blockIdx.y;
    const float* W = (t == 0) ? Wq : (t == 1) ? Wk : Wv;
    int idx = blockIdx.x * 256 + threadIdx.x;
    float v = W[idx];
    __half h, m;
    f16_split2(v, h, m);
    g_wh[t * CC * CC + idx] = h;
    g_wm[t * CC * CC + idx] = m;
}

__global__ void bias_copy_kernel(const float* __restrict__ bq,
                                 const float* __restrict__ bk,
                                 const float* __restrict__ bv)
{
    int i = threadIdx.x;
    g_bias[i]          = bq[i];
    g_bias[CC + i]     = bk[i];
    g_bias[2 * CC + i] = bv[i];
}

__global__ void xprep_kernel(const float* __restrict__ x1,
                             const float* __restrict__ x2)
{
    __shared__ float tile[32][33];
    int z = blockIdx.z;
    int b = z & 3;
    const float* src = ((z < 4) ? x1 : x2) + (size_t)b * CC * NN;
    __half* dh = ((z < 4) ? g_x1h : g_x2h) + (size_t)b * NN * CC;
    __half* dm = ((z < 4) ? g_x1m : g_x2m) + (size_t)b * NN * CC;
    int i0 = blockIdx.x * 32;
    int c0 = blockIdx.y * 32;
    int tx = threadIdx.x, ty = threadIdx.y;
#pragma unroll
    for (int u = 0; u < 32; u += 8)
        tile[ty + u][tx] = src[(size_t)(c0 + ty + u) * NN + i0 + tx];
    __syncthreads();
#pragma unroll
    for (int u = 0; u < 32; u += 8) {
        float v = tile[tx][ty + u];
        __half h, m;
        f16_split2(v, h, m);
        size_t idx = (size_t)(i0 + ty + u) * CC + c0 + tx;
        dh[idx] = h;
        dm[idx] = m;
    }
}

// ---------------------------------------------------------------------------
// Single-term warp MMA, warp tile 32x64, k-chunk 64. Used by ALL kernels;
// term selection is folded into a_off / b_off. 6 LDSM4 + 16 HMMA per kk.
// ---------------------------------------------------------------------------
__device__ __forceinline__ void mma_stage1(uint32_t st, uint32_t a_off, uint32_t b_off,
                                           float acc[2][8][4])
{
#pragma unroll
    for (int kk = 0; kk < 4; kk++) {
        uint32_t ah[2][4];
#pragma unroll
        for (int mi = 0; mi < 2; mi++) {
            uint32_t ad = st + a_off + mi * (16 * RSTR) + kk * 32;
            LDSM4(ah[mi][0], ah[mi][1], ah[mi][2], ah[mi][3], ad);
        }
#pragma unroll
        for (int ng = 0; ng < 4; ng++) {
            uint32_t bd = st + b_off + ng * (16 * RSTR) + kk * 32;
            uint32_t bh[4];
            LDSM4(bh[0], bh[1], bh[2], bh[3], bd);
#pragma unroll
            for (int mi = 0; mi < 2; mi++) {
                mma_f16(acc[mi][ng * 2],     ah[mi], bh[0], bh[1]);
                mma_f16(acc[mi][ng * 2 + 1], ah[mi], bh[2], bh[3]);
            }
        }
    }
}

// Loader (2-term, 512 threads, 128-row tiles of 128B data):
// thread -> (row = tid>>2, seg = (tid&3)*32); 2 CP16 per array.
#define ISSUE2(stg_base, goff) do {                               \
        uint32_t dA = s_a + (stg_base);                           \
        uint32_t dB = s_b + (stg_base);                           \
        CP16(dA,              gA_h + (goff));                     \
        CP16(dA + 16,         gA_h + (goff) + 16);                \
        CP16(dA + A2M_D,      gA_m + (goff));                     \
        CP16(dA + A2M_D + 16, gA_m + (goff) + 16);                \
        CP16(dB,              gB_h + (goff));                     \
        CP16(dB + 16,         gB_h + (goff) + 16);                \
        CP16(dB + B2M_D,      gB_m + (goff));                     \
        CP16(dB + B2M_D + 16, gB_m + (goff) + 16);                \
        CP_COMMIT();                                              \
    } while (0)

#define ACC_INIT8(a) do {                                         \
    _Pragma("unroll") for (int i = 0; i < 2; i++)                 \
    _Pragma("unroll") for (int j = 0; j < 8; j++)                 \
    _Pragma("unroll") for (int r = 0; r < 4; r++) (a)[i][j][r] = 0.0f; \
} while (0)

// Term combine via smem (aliases dead stage buffers).
// Pair = (wm, wn); wt=1 warp dumps D2, wt=0 warp merges into D1.
#define COMBINE_TERMS(acc)                                                   \
    do {                                                                     \
        float* cmb = (float*)sm + (size_t)(wid >> 1) * 2048 + lane * 64;     \
        __syncthreads();                                                     \
        if (wt == 1) {                                                       \
            _Pragma("unroll") for (int mi = 0; mi < 2; mi++)                 \
            _Pragma("unroll") for (int np = 0; np < 8; np++)                 \
            _Pragma("unroll") for (int r = 0; r < 4; r++)                    \
                cmb[mi * 32 + np * 4 + r] = (acc)[mi][np][r];                \
        }                                                                    \
        __syncthreads();                                                     \
        if (wt == 0) {                                                       \
            _Pragma("unroll") for (int mi = 0; mi < 2; mi++)                 \
            _Pragma("unroll") for (int np = 0; np < 8; np++)                 \
            _Pragma("unroll") for (int r = 0; r < 4; r++) {                  \
                float d2 = cmb[mi * 32 + np * 4 + r];                        \
                (acc)[mi][np][r] = fmaf(d2 - (acc)[mi][np][r], INV_S,        \
                                        (acc)[mi][np][r]);                   \
            }                                                                \
        }                                                                    \
    } while (0)

// ---------------------------------------------------------------------------
// Kernel: QKV projection, term-split warps, 512 threads, tile 128x128.
// grid (32, 2, 12). warp = (wm rows, wn 64-col band, wt term).
// ---------------------------------------------------------------------------
__global__ void __launch_bounds__(512, 1) proj_mma()
{
    extern __shared__ char sm[];
    __shared__ float bias_s[128];
    uint32_t sb = smem_u32(sm);
    int tid = threadIdx.x, wid = tid >> 5, lane = tid & 31;
    int z = blockIdx.z;
    int b = z / 3, t = z % 3;
    int i0 = blockIdx.x * 128;
    int o0 = blockIdx.y * 128;
    int wt = wid & 1, wn = (wid >> 1) & 1, wm = wid >> 2;

    const __half* Xh = ((t == 0) ? g_x1h : g_x2h) + (size_t)b * NN * CC;
    const __half* Xm = ((t == 0) ? g_x1m : g_x2m) + (size_t)b * NN * CC;
    const __half* Wh = g_wh + t * CC * CC;
    const __half* Wm = g_wm + t * CC * CC;

    if (tid < 128) bias_s[tid] = g_bias[t * CC + o0 + tid];

    int lrow = tid >> 2, lseg = (tid & 3) * 32;
    const char* gA_h = (const char*)(Xh + (size_t)(i0 + lrow) * CC) + lseg;
    const char* gA_m = (const char*)(Xm + (size_t)(i0 + lrow) * CC) + lseg;
    const char* gB_h = (const char*)(Wh + (size_t)(o0 + lrow) * CC) + lseg;
    const char* gB_m = (const char*)(Wm + (size_t)(o0 + lrow) * CC) + lseg;
    uint32_t s_a = sb + lrow * RSTR + lseg;
    uint32_t s_b = sb + B2_OFF + lrow * RSTR + lseg;

    uint32_t a_off = (wm * 32 + (lane & 15)) * RSTR + ((lane >> 4) << 4)
                   + (wt ? A2M_D : 0);
    uint32_t b_off = (wn * 64 + (lane & 7) + ((lane >> 4) << 3)) * RSTR
                   + (((lane >> 3) & 1) << 4) + B2_OFF + (wt ? B2M_D : 0);

    float acc[2][8][4];
    ACC_INIT8(acc);

    ISSUE2(0, 0);
    ISSUE2(STG2, 128);
    uint32_t bA = 0, bB = STG2, bC = 2 * STG2;
    for (int ch = 0; ch < 4; ch++) {
        if (ch < 3) CP_WAIT1(); else CP_WAIT0();
        __syncthreads();
        if (ch < 2) ISSUE2(bC, (size_t)(ch + 2) * 128);
        mma_stage1(sb + bA, a_off, b_off, acc);
        uint32_t tmp = bA; bA = bB; bB = bC; bC = tmp;
    }
    COMBINE_TERMS(acc);

    if (t < 2) {
        __half* dh = ((t == 0) ? g_qh : g_kh) + (size_t)b * NN * CC;
        __half* dm = ((t == 0) ? g_qm : g_km) + (size_t)b * NN * CC;
        if (wt == 0) {
#pragma unroll
            for (int mi = 0; mi < 2; mi++) {
#pragma unroll
                for (int np = 0; np < 8; np++) {
                    int col = wn * 64 + np * 8 + (lane & 3) * 2;
                    float bc0 = bias_s[col], bc1 = bias_s[col + 1];
#pragma unroll
                    for (int rh = 0; rh < 2; rh++) {
                        int row = i0 + wm * 32 + mi * 16 + rh * 8 + (lane >> 2);
                        float v0 = acc[mi][np][rh * 2]     + bc0;
                        float v1 = acc[mi][np][rh * 2 + 1] + bc1;
                        __half h0, m0, h1, m1;
                        f16_split2(v0, h0, m0);
                        f16_split2(v1, h1, m1);
                        union { __half e[2]; uint32_t u; } ph, pmu;
                        ph.e[0] = h0;  ph.e[1] = h1;
                        pmu.e[0] = m0; pmu.e[1] = m1;
                        *(uint32_t*)(dh + (size_t)row * CC + o0 + col) = ph.u;
                        *(uint32_t*)(dm + (size_t)row * CC + o0 + col) = pmu.u;
                    }
                }
            }
        }
    } else {
        __half* dv = g_vt + (size_t)b * CC * NN;
        float* smt = (float*)sm;   // 128 x 132 fp32 (aliases cmb region; resync)
        __syncthreads();
        if (wt == 0) {
#pragma unroll
            for (int mi = 0; mi < 2; mi++) {
                int r0 = wm * 32 + mi * 16 + (lane >> 2);
#pragma unroll
                for (int np = 0; np < 8; np++) {
                    int c = wn * 64 + np * 8 + (lane & 3) * 2;
                    float b0 = bias_s[c], b1 = bias_s[c + 1];
                    smt[(c + 0) * 132 + r0]     = acc[mi][np][0] + b0;
                    smt[(c + 1) * 132 + r0]     = acc[mi][np][1] + b1;
                    smt[(c + 0) * 132 + r0 + 8] = acc[mi][np][2] + b0;
                    smt[(c + 1) * 132 + r0 + 8] = acc[mi][np][3] + b1;
                }
            }
        }
        __syncthreads();
        {
            int cl = tid >> 2, part = tid & 3;
            const float* sp = smt + cl * 132 + part * 32;
            size_t go = (size_t)(o0 + cl) * NN + i0 + part * 32;
            union { __half e[32]; uint4 v[4]; } uh;
#pragma unroll
            for (int u = 0; u < 32; u++) uh.e[u] = __float2half_rn(sp[u]);
#pragma unroll
            for (int u = 0; u < 4; u++)
                *(uint4*)(dv + go + u * 8) = uh.v[u];
        }
    }
}

// ---------------------------------------------------------------------------
// Kernel: scores, term-split warps, 512 threads, tile 128x128, k-chunk 64.
// grid (32, 32, 4). Fused stats + fp16 P store (wt=0 warps).
// ---------------------------------------------------------------------------
__global__ void __launch_bounds__(512, 1) scores_mma()
{
    extern __shared__ char sm[];
    __shared__ float pm2[128][2], pl2[128][2];
    uint32_t sb = smem_u32(sm);
    int tid = threadIdx.x, wid = tid >> 5, lane = tid & 31;
    int b = blockIdx.z, i0 = blockIdx.x * 128, j0 = blockIdx.y * 128;
    int wt = wid & 1, wn = (wid >> 1) & 1, wm = wid >> 2;

    const __half* Qh = g_qh + (size_t)b * NN * CC;
    const __half* Qm = g_qm + (size_t)b * NN * CC;
    const __half* Kh = g_kh + (size_t)b * NN * CC;
    const __half* Km = g_km + (size_t)b * NN * CC;
    __half* P = g_p + (size_t)b * NN * NN;

    int lrow = tid >> 2, lseg = (tid & 3) * 32;
    const char* gA_h = (const char*)(Qh + (size_t)(i0 + lrow) * CC) + lseg;
    const char* gA_m = (const char*)(Qm + (size_t)(i0 + lrow) * CC) + lseg;
    const char* gB_h = (const char*)(Kh + (size_t)(j0 + lrow) * CC) + lseg;
    const char* gB_m = (const char*)(Km + (size_t)(j0 + lrow) * CC) + lseg;
    uint32_t s_a = sb + lrow * RSTR + lseg;
    uint32_t s_b = sb + B2_OFF + lrow * RSTR + lseg;

    uint32_t a_off = (wm * 32 + (lane & 15)) * RSTR + ((lane >> 4) << 4)
                   + (wt ? A2M_D : 0);
    uint32_t b_off = (wn * 64 + (lane & 7) + ((lane >> 4) << 3)) * RSTR
                   + (((lane >> 3) & 1) << 4) + B2_OFF + (wt ? B2M_D : 0);

    float acc[2][8][4];
    ACC_INIT8(acc);

    ISSUE2(0, 0);
    ISSUE2(STG2, 128);
    uint32_t bA = 0, bB = STG2, bC = 2 * STG2;
    for (int ch = 0; ch < 4; ch++) {
        if (ch < 3) CP_WAIT1(); else CP_WAIT0();
        __syncthreads();
        if (ch < 2) ISSUE2(bC, (size_t)(ch + 2) * 128);
        mma_stage1(sb + bA, a_off, b_off, acc);
        uint32_t tmp = bA; bA = bB; bB = bC; bC = tmp;
    }
    COMBINE_TERMS(acc);

    // Stats + P store (wt=0 warps own combined D for 32 rows x 64 cols)
    int q = lane >> 2, qt = lane & 3;
    float mloc[2][2];
    if (wt == 0) {
#pragma unroll
        for (int mi = 0; mi < 2; mi++)
#pragma unroll
            for (int rh = 0; rh < 2; rh++) {
                float m = -1e30f;
#pragma unroll
                for (int np = 0; np < 8; np++)
                    m = fmaxf(m, fmaxf(acc[mi][np][rh * 2], acc[mi][np][rh * 2 + 1]));
                mloc[mi][rh] = m;
            }
#pragma unroll
        for (int d = 1; d <= 2; d <<= 1)
#pragma unroll
            for (int mi = 0; mi < 2; mi++)
#pragma unroll
                for (int rh = 0; rh < 2; rh++)
                    mloc[mi][rh] = fmaxf(mloc[mi][rh],
                                         __shfl_xor_sync(0xffffffffu, mloc[mi][rh], d));
        if (qt == 0)
#pragma unroll
            for (int mi = 0; mi < 2; mi++)
#pragma unroll
                for (int rh = 0; rh < 2; rh++)
                    pm2[wm * 32 + mi * 16 + rh * 8 + q][wn] = mloc[mi][rh];
    }
    __syncthreads();

    float mrow[2][2], srow[2][2];
    if (wt == 0) {
#pragma unroll
        for (int mi = 0; mi < 2; mi++)
#pragma unroll
            for (int rh = 0; rh < 2; rh++) {
                int row = wm * 32 + mi * 16 + rh * 8 + q;
                float m = fmaxf(pm2[row][0], pm2[row][1]);
                mrow[mi][rh] = m;
                __half* prow = P + (size_t)(i0 + row) * NN + j0 + wn * 64 + qt * 2;
                float s = 0.0f;
#pragma unroll
                for (int np = 0; np < 8; np++) {
                    float e0 = fast_exp(acc[mi][np][rh * 2]     - m);
                    float e1 = fast_exp(acc[mi][np][rh * 2 + 1] - m);
                    s += e0 + e1;
                    *(__half2*)(prow + np * 8) = __floats2half2_rn(e0, e1);
                }
                srow[mi][rh] = s;
            }
#pragma unroll
        for (int d = 1; d <= 2; d <<= 1)
#pragma unroll
            for (int mi = 0; mi < 2; mi++)
#pragma unroll
                for (int rh = 0; rh < 2; rh++)
                    srow[mi][rh] += __shfl_xor_sync(0xffffffffu, srow[mi][rh], d);
        if (qt == 0)
#pragma unroll
            for (int mi = 0; mi < 2; mi++)
#pragma unroll
                for (int rh = 0; rh < 2; rh++)
                    pl2[wm * 32 + mi * 16 + rh * 8 + q][wn] = srow[mi][rh];
    }
    __syncthreads();
    if (wt == 0 && wn == 0 && qt == 0)
#pragma unroll
        for (int mi = 0; mi < 2; mi++)
#pragma unroll
            for (int rh = 0; rh < 2; rh++) {
                int row = wm * 32 + mi * 16 + rh * 8 + q;
                size_t idx = ((size_t)b * NN + i0 + row) * 32 + blockIdx.y;
                g_pm[idx] = fmaxf(pm2[row][0], pm2[row][1]);
                g_pl[idx] = pl2[row][0] + pl2[row][1];
            }
}

// ---------------------------------------------------------------------------
// Kernel: merge 32 partials per row. One warp per row.
// ---------------------------------------------------------------------------
__global__ __launch_bounds__(256) void merge_kernel()
{
    int row  = blockIdx.x * 8 + (threadIdx.x >> 5);
    int lane = threadIdx.x & 31;
    float m_t = g_pm[(size_t)row * 32 + lane];
    float l_t = g_pl[(size_t)row * 32 + lane];
    float m = m_t;
#pragma unroll
    for (int d = 16; d > 0; d >>= 1) m = fmaxf(m, __shfl_xor_sync(0xffffffffu, m, d));
    float l = l_t * fast_exp(m_t - m);
#pragma unroll
    for (int d = 16; d > 0; d >>= 1) l += __shfl_xor_sync(0xffffffffu, l, d);
    if (lane == 0) { g_m[row] = m; g_li[row] = 1.0f / l; }
}

// ---------------------------------------------------------------------------
// Kernel: PV, 1-term, k-chunk 64 (64 rounds). P pre-exponentiated, rescaled
// per (row, 128-col tile). grid (32, 1, 4), 512 threads.
// ---------------------------------------------------------------------------
__global__ void __launch_bounds__(512, 1) pv_mma(float* __restrict__ out)
{
    extern __shared__ char sm[];
    __shared__ float m_s[128], li_s[128];
    __shared__ float pm_s[128][32];
    uint32_t sb = smem_u32(sm);
    int tid = threadIdx.x, wid = tid >> 5, lane = tid & 31;
    int b = blockIdx.z, i0 = blockIdx.x * 128;
    int wm = wid & 3, wn = wid >> 2;

    const __half* P = g_p + (size_t)b * NN * NN;
    const __half* V = g_vt + (size_t)b * CC * NN;

    if (tid < 128) {
        m_s[tid]  = g_m[b * NN + i0 + tid];
        li_s[tid] = g_li[b * NN + i0 + tid];
    }
#pragma unroll
    for (int idx = tid; idx < 128 * 32; idx += 512)
        pm_s[idx >> 5][idx & 31] = g_pm[((size_t)b * NN + i0 + (idx >> 5)) * 32 + (idx & 31)];

    int arow = tid >> 2, aq = tid & 3;
    const __half* gP = P + (size_t)(i0 + arow) * NN + aq * 16;
    uint32_t s_aw_off = (uint32_t)arow * RSTR + aq * 32;

    int brow = tid >> 1, bhalf = (tid & 1) * 64;
    const char* gv = (const char*)(V + (size_t)brow * NN) + bhalf;
    uint32_t s_b = sb + PB_OFF + brow * RSTR + bhalf;

    uint32_t a_off = (wm * 32 + (lane & 15)) * RSTR + ((lane >> 4) << 4);
    uint32_t b_off = (wn * 64 + (lane & 7) + ((lane >> 4) << 3)) * RSTR
                   + (((lane >> 3) & 1) << 4) + PB_OFF;

    float acc[2][8][4];
    ACC_INIT8(acc);

#define ISSUE_V(stg_base, goff) do {                              \
        uint32_t d = s_b + (stg_base);                            \
        CP16(d,      gv + (goff));                                \
        CP16(d + 16, gv + (goff) + 16);                           \
        CP16(d + 32, gv + (goff) + 32);                           \
        CP16(d + 48, gv + (goff) + 48);                           \
        CP_COMMIT();                                              \
    } while (0)

#define PRODUCE_A(stg_base, chk) do {                                       \
        float scf = fast_exp(pm_s[arow][(chk) >> 1] - mrow);                \
        __half2 sc2 = __float2half2_rn(scf);                                \
        union { __half2 h[4]; uint4 v; } u0, u1;                            \
        u0.v = sv[0]; u1.v = sv[1];                                         \
        u0.h[0] = __hmul2(u0.h[0], sc2); u0.h[1] = __hmul2(u0.h[1], sc2);   \
        u0.h[2] = __hmul2(u0.h[2], sc2); u0.h[3] = __hmul2(u0.h[3], sc2);   \
        u1.h[0] = __hmul2(u1.h[0], sc2); u1.h[1] = __hmul2(u1.h[1], sc2);   \
        u1.h[2] = __hmul2(u1.h[2], sc2); u1.h[3] = __hmul2(u1.h[3], sc2);   \
        uint32_t doff = s_aw_off + (stg_base);                              \
        *(uint4*)(sm + doff)      = u0.v;                                   \
        *(uint4*)(sm + doff + 16) = u1.v;                                   \
    } while (0)

    uint4 sv[2];
    {
        const uint4* p = (const uint4*)gP;
        sv[0] = p[0]; sv[1] = p[1];
    }
    ISSUE_V(0, 0);
    ISSUE_V(PSTG, 128);
    __syncthreads();
    float mrow = m_s[arow];
    PRODUCE_A(0, 0);
    {
        const uint4* p = (const uint4*)(gP + 64);
        sv[0] = p[0]; sv[1] = p[1];
    }

    uint32_t bA = 0, bB = PSTG, bC = 2 * PSTG;
    for (int ch = 0; ch < 64; ch++) {
        if (ch < 63) CP_WAIT1(); else CP_WAIT0();
        __syncthreads();
        if (ch < 63) PRODUCE_A(bB, ch + 1);
        if (ch < 62) {
            ISSUE_V(bC, (size_t)(ch + 2) * 128);
            const uint4* p = (const uint4*)(gP + (size_t)(ch + 2) * 64);
            sv[0] = p[0]; sv[1] = p[1];
        }
        mma_stage1(sb + bA, a_off, b_off, acc);
        uint32_t tmp = bA; bA = bB; bB = bC; bC = tmp;
    }
#undef ISSUE_V
#undef PRODUCE_A

    float* smt = (float*)sm;
#pragma unroll
    for (int h = 0; h < 2; h++) {
        __syncthreads();
        if ((wn >> 1) == h) {
#pragma unroll
            for (int mi = 0; mi < 2; mi++) {
                int r0 = wm * 32 + mi * 16 + (lane >> 2);
                float l0 = li_s[r0], l1 = li_s[r0 + 8];
#pragma unroll
                for (int np = 0; np < 8; np++) {
                    int c = (wn & 1) * 64 + np * 8 + (lane & 3) * 2;
                    smt[(c + 0) * 132 + r0]     = acc[mi][np][0] * l0;
                    smt[(c + 1) * 132 + r0]     = acc[mi][np][1] * l0;
                    smt[(c + 0) * 132 + r0 + 8] = acc[mi][np][2] * l1;
                    smt[(c + 1) * 132 + r0 + 8] = acc[mi][np][3] * l1;
                }
            }
        }
        __syncthreads();
        {
            int cl = tid >> 2, part = tid & 3;
            float* op = out + ((size_t)b * CC + h * 128 + cl) * NN + i0 + part * 32;
            const float* sp = smt + cl * 132 + part * 32;
#pragma unroll
            for (int u = 0; u < 8; u++)
                ((float4*)op)[u] = ((const float4*)sp)[u];
        }
    }
}

extern "C" void kernel_launch(void* const* d_in, const int* in_sizes, int n_in,
                              void* d_out, int out_size)
{
    const float* x1 = (const float*)d_in[0];
    const float* x2 = (const float*)d_in[1];
    const float* Wq = (const float*)d_in[2];
    const float* bq = (const float*)d_in[3];
    const float* Wk = (const float*)d_in[4];
    const float* bk = (const float*)d_in[5];
    const float* Wv = (const float*)d_in[6];
    const float* bv = (const float*)d_in[7];
    float* out = (float*)d_out;

    cudaFuncSetAttribute(proj_mma,   cudaFuncAttributeMaxDynamicSharedMemorySize, SMEM_2);
    cudaFuncSetAttribute(scores_mma, cudaFuncAttributeMaxDynamicSharedMemorySize, SMEM_2);
    cudaFuncSetAttribute(pv_mma,     cudaFuncAttributeMaxDynamicSharedMemorySize, SMEM_P);

    wsplit_kernel<<<dim3(256, 3), 256>>>(Wq, Wk, Wv);
    bias_copy_kernel<<<1, 256>>>(bq, bk, bv);
    xprep_kernel<<<dim3(NN / 32, CC / 32, 2 * BB), dim3(32, 8)>>>(x1, x2);
    proj_mma<<<dim3(NN / 128, CC / 128, BB * 3), 512, SMEM_2>>>();
    scores_mma<<<dim3(NN / 128, NN / 128, BB), 512, SMEM_2>>>();
    merge_kernel<<<BB * NN / 8, 256>>>();
    pv_mma<<<dim3(NN / 128, 1, BB), 512, SMEM_P>>>(out);
}

// round 16
// speedup vs baseline: 1.2512x; 1.2512x over previous
#include <cuda_runtime.h>
#include <cuda_fp16.h>
#include <cstdint>

#define BB 4
#define CC 256
#define NN 4096

#define SSPLIT 128.0f
#define INV_S  0.0078125f     // 1/128

// ---------------------------------------------------------------------------
// Scratch. 2-term operands: (h, m) with m = fp16(h + s*(v-h)), s=128.
// X = D1 + (D2-D1)/s reconstructs hi·hi + cross terms.
// ---------------------------------------------------------------------------
__device__ __half g_x1h[(size_t)BB * NN * CC];
__device__ __half g_x1m[(size_t)BB * NN * CC];
__device__ __half g_x2h[(size_t)BB * NN * CC];
__device__ __half g_x2m[(size_t)BB * NN * CC];
__device__ __half g_wh[3 * CC * CC];
__device__ __half g_wm[3 * CC * CC];
__device__ float  g_bias[3 * CC];
__device__ __half g_qh[(size_t)BB * NN * CC];
__device__ __half g_qm[(size_t)BB * NN * CC];
__device__ __half g_kh[(size_t)BB * NN * CC];
__device__ __half g_km[(size_t)BB * NN * CC];
__device__ __half g_vt[(size_t)BB * CC * NN];     // V^T fp16 [b][c][j]
__device__ __half g_p[(size_t)BB * NN * NN];      // P = exp(S - m_tile), fp16
__device__ float g_pm[(size_t)BB * NN * 32];      // per-(row, 128-col tile) max
__device__ float g_pl[(size_t)BB * NN * 32];
__device__ float g_m [BB * NN];
__device__ float g_li[BB * NN];

// ---------------------------------------------------------------------------
// PTX helpers
// ---------------------------------------------------------------------------
__device__ __forceinline__ uint32_t smem_u32(const void* p) {
    uint32_t a;
    asm("{ .reg .u64 t; cvta.to.shared.u64 t, %1; cvt.u32.u64 %0, t; }"
        : "=r"(a) : "l"(p));
    return a;
}

#define CP16(smem, gptr) \
    asm volatile("cp.async.ca.shared.global [%0], [%1], 16;" \
                 :: "r"(smem), "l"(gptr) : "memory")
#define CP_COMMIT() asm volatile("cp.async.commit_group;" ::: "memory")
#define CP_WAIT1()  asm volatile("cp.async.wait_group 1;" ::: "memory")
#define CP_WAIT0()  asm volatile("cp.async.wait_group 0;" ::: "memory")

#define LDSM4(r0, r1, r2, r3, addr) \
    asm volatile("ldmatrix.sync.aligned.m8n8.x4.shared.b16 {%0,%1,%2,%3}, [%4];" \
                 : "=r"(r0), "=r"(r1), "=r"(r2), "=r"(r3) : "r"(addr))

__device__ __forceinline__ void mma_f16(float* d, const uint32_t* a,
                                        uint32_t b0, uint32_t b1) {
    asm volatile(
        "mma.sync.aligned.m16n8k16.row.col.f32.f16.f16.f32 "
        "{%0,%1,%2,%3}, {%4,%5,%6,%7}, {%8,%9}, {%0,%1,%2,%3};"
        : "+f"(d[0]), "+f"(d[1]), "+f"(d[2]), "+f"(d[3])
        : "r"(a[0]), "r"(a[1]), "r"(a[2]), "r"(a[3]), "r"(b0), "r"(b1));
}

// k-chunk 64 fp16 = 128B data per row, padded to 144B (144 mod 128 = 16 ->
// 8 successive rows hit all 8 16B banks: conflict-free ldmatrix).
#define RSTR    144
// scores/proj stage: Ah(18432) Am(18432) Bh(18432) Bm(18432) = 73728, x3
#define A2M_D   18432
#define B2_OFF  36864
#define B2M_D   18432
#define STG2    73728
#define SMEM_2  (3 * STG2)     // 221184 (1 CTA/SM)
// pv stage: P(18432) V(256 rows: 36864) = 55296, x3
#define PB_OFF  18432
#define PSTG    55296
#define SMEM_P  (3 * PSTG)     // 165888

__device__ __forceinline__ float fast_exp(float x) {
    float y = fmaxf(x, -87.0f) * 1.4426950408889634f;
    float z = __fadd_rn(y, 12582912.0f);
    int   k = __float_as_int(z) - 0x4B400000;
    float f = __fsub_rn(y, __fsub_rn(z, 12582912.0f));
    float p =             1.33335581e-3f;
    p = fmaf(p, f, 9.61812910e-3f);
    p = fmaf(p, f, 5.55041087e-2f);
    p = fmaf(p, f, 2.40226507e-1f);
    p = fmaf(p, f, 6.93147181e-1f);
    p = fmaf(p, f, 1.0f);
    return __int_as_float(__float_as_int(p) + (k << 23));
}

__device__ __forceinline__ void f16_split2(float v, __half& h, __half& m) {
    h = __float2half_rn(v);
    float hf = __half2float(h);
    m = __float2half_rn(fmaf(SSPLIT, v - hf, hf));
}

// ---------------------------------------------------------------------------
// Prep kernels (wsplit now also stages the biases: one fewer launch)
// ---------------------------------------------------------------------------
__global__ void wsplit_kernel(const float* __restrict__ Wq,
                              const float* __restrict__ Wk,
                              const float* __restrict__ Wv,
                              const float* __restrict__ bq,
                              const float* __restrict__ bk,
                              const float* __restrict__ bv)
{
    int t = blockIdx.y;
    const float* W = (t == 0) ? Wq : (t == 1) ? Wk : Wv;
    int idx = blockIdx.x * 256 + threadIdx.x;
    float v = W[idx];
    __half h, m;
    f16_split2(v, h, m);
    g_wh[t * CC * CC + idx] = h;
    g_wm[t * CC * CC + idx] = m;
    if (blockIdx.x == 0) {
        const float* bias = (t == 0) ? bq : (t == 1) ? bk : bv;
        g_bias[t * CC + threadIdx.x] = bias[threadIdx.x];
    }
}

__global__ void xprep_kernel(const float* __restrict__ x1,
                             const float* __restrict__ x2)
{
    __shared__ float tile[32][33];
    int z = blockIdx.z;
    int b = z & 3;
    const float* src = ((z < 4) ? x1 : x2) + (size_t)b * CC * NN;
    __half* dh = ((z < 4) ? g_x1h : g_x2h) + (size_t)b * NN * CC;
    __half* dm = ((z < 4) ? g_x1m : g_x2m) + (size_t)b * NN * CC;
    int i0 = blockIdx.x * 32;
    int c0 = blockIdx.y * 32;
    int tx = threadIdx.x, ty = threadIdx.y;
#pragma unroll
    for (int u = 0; u < 32; u += 8)
        tile[ty + u][tx] = src[(size_t)(c0 + ty + u) * NN + i0 + tx];
    __syncthreads();
#pragma unroll
    for (int u = 0; u < 32; u += 8) {
        float v = tile[tx][ty + u];
        __half h, m;
        f16_split2(v, h, m);
        size_t idx = (size_t)(i0 + ty + u) * CC + c0 + tx;
        dh[idx] = h;
        dm[idx] = m;
    }
}

// ---------------------------------------------------------------------------
// 2-term dual-acc warp MMA, warp tile 32x32, k-chunk 64 (kk 0..3).
// ---------------------------------------------------------------------------
__device__ __forceinline__ void mma_stage2t(uint32_t st, uint32_t a_off, uint32_t b_off,
                                            float acc1[2][4][4], float acc2[2][4][4])
{
#pragma unroll
    for (int kk = 0; kk < 4; kk++) {
        uint32_t ah[2][4], am[2][4];
#pragma unroll
        for (int mi = 0; mi < 2; mi++) {
            uint32_t ad = st + a_off + mi * (16 * RSTR) + kk * 32;
            LDSM4(ah[mi][0], ah[mi][1], ah[mi][2], ah[mi][3], ad);
            LDSM4(am[mi][0], am[mi][1], am[mi][2], am[mi][3], ad + A2M_D);
        }
#pragma unroll
        for (int ng = 0; ng < 2; ng++) {
            uint32_t bd = st + b_off + ng * (16 * RSTR) + kk * 32;
            uint32_t bh[4], bm[4];
            LDSM4(bh[0], bh[1], bh[2], bh[3], bd);
            LDSM4(bm[0], bm[1], bm[2], bm[3], bd + B2M_D);
#pragma unroll
            for (int mi = 0; mi < 2; mi++) {
                mma_f16(acc1[mi][ng * 2],     ah[mi], bh[0], bh[1]);
                mma_f16(acc1[mi][ng * 2 + 1], ah[mi], bh[2], bh[3]);
                mma_f16(acc2[mi][ng * 2],     am[mi], bm[0], bm[1]);
                mma_f16(acc2[mi][ng * 2 + 1], am[mi], bm[2], bm[3]);
            }
        }
    }
}

// 1-term PV: warp tile 32x64, k-chunk 64.
__device__ __forceinline__ void mma_stage1(uint32_t st, uint32_t a_off, uint32_t b_off,
                                           float acc[2][8][4])
{
#pragma unroll
    for (int kk = 0; kk < 4; kk++) {
        uint32_t ah[2][4];
#pragma unroll
        for (int mi = 0; mi < 2; mi++) {
            uint32_t ad = st + a_off + mi * (16 * RSTR) + kk * 32;
            LDSM4(ah[mi][0], ah[mi][1], ah[mi][2], ah[mi][3], ad);
        }
#pragma unroll
        for (int ng = 0; ng < 4; ng++) {
            uint32_t bd = st + b_off + ng * (16 * RSTR) + kk * 32;
            uint32_t bh[4];
            LDSM4(bh[0], bh[1], bh[2], bh[3], bd);
#pragma unroll
            for (int mi = 0; mi < 2; mi++) {
                mma_f16(acc[mi][ng * 2],     ah[mi], bh[0], bh[1]);
                mma_f16(acc[mi][ng * 2 + 1], ah[mi], bh[2], bh[3]);
            }
        }
    }
}

// Loader (2-term, 512 threads, 128-row tiles of 128B data):
// thread -> (row = tid>>2, seg = (tid&3)*32); 2 CP16 per array.
#define ISSUE2(stg_base, goff) do {                               \
        uint32_t dA = s_a + (stg_base);                           \
        uint32_t dB = s_b + (stg_base);                           \
        CP16(dA,              gA_h + (goff));                     \
        CP16(dA + 16,         gA_h + (goff) + 16);                \
        CP16(dA + A2M_D,      gA_m + (goff));                     \
        CP16(dA + A2M_D + 16, gA_m + (goff) + 16);                \
        CP16(dB,              gB_h + (goff));                     \
        CP16(dB + 16,         gB_h + (goff) + 16);                \
        CP16(dB + B2M_D,      gB_m + (goff));                     \
        CP16(dB + B2M_D + 16, gB_m + (goff) + 16);                \
        CP_COMMIT();                                              \
    } while (0)

#define ACC_INIT4(a) do {                                         \
    _Pragma("unroll") for (int i = 0; i < 2; i++)                 \
    _Pragma("unroll") for (int j = 0; j < 4; j++)                 \
    _Pragma("unroll") for (int r = 0; r < 4; r++) (a)[i][j][r] = 0.0f; \
} while (0)

#define ACC_COMBINE4(a1, a2) do {                                 \
    _Pragma("unroll") for (int i = 0; i < 2; i++)                 \
    _Pragma("unroll") for (int j = 0; j < 4; j++)                 \
    _Pragma("unroll") for (int r = 0; r < 4; r++)                 \
        (a1)[i][j][r] = fmaf((a2)[i][j][r] - (a1)[i][j][r], INV_S, (a1)[i][j][r]); \
} while (0)

// ---------------------------------------------------------------------------
// Kernel: QKV projection, 2-term, 512 threads, tile 128x128, k-chunk 64.
// grid (32, 2, 12). t<2: write Q/K (h,m). t==2: transpose -> V^T fp16.
// ---------------------------------------------------------------------------
__global__ void __launch_bounds__(512, 1) proj_mma()
{
    extern __shared__ char sm[];
    __shared__ float bias_s[128];
    uint32_t sb = smem_u32(sm);
    int tid = threadIdx.x, wid = tid >> 5, lane = tid & 31;
    int z = blockIdx.z;
    int b = z / 3, t = z % 3;
    int i0 = blockIdx.x * 128;
    int o0 = blockIdx.y * 128;
    int wm = wid & 3, wn = wid >> 2;

    const __half* Xh = ((t == 0) ? g_x1h : g_x2h) + (size_t)b * NN * CC;
    const __half* Xm = ((t == 0) ? g_x1m : g_x2m) + (size_t)b * NN * CC;
    const __half* Wh = g_wh + t * CC * CC;
    const __half* Wm = g_wm + t * CC * CC;

    if (tid < 128) bias_s[tid] = g_bias[t * CC + o0 + tid];

    int lrow = tid >> 2, lseg = (tid & 3) * 32;
    const char* gA_h = (const char*)(Xh + (size_t)(i0 + lrow) * CC) + lseg;
    const char* gA_m = (const char*)(Xm + (size_t)(i0 + lrow) * CC) + lseg;
    const char* gB_h = (const char*)(Wh + (size_t)(o0 + lrow) * CC) + lseg;
    const char* gB_m = (const char*)(Wm + (size_t)(o0 + lrow) * CC) + lseg;
    uint32_t s_a = sb + lrow * RSTR + lseg;
    uint32_t s_b = sb + B2_OFF + lrow * RSTR + lseg;

    uint32_t a_off = (wm * 32 + (lane & 15)) * RSTR + ((lane >> 4) << 4);
    uint32_t b_off = (wn * 32 + (lane & 7) + ((lane >> 4) << 3)) * RSTR
                   + (((lane >> 3) & 1) << 4) + B2_OFF;

    float acc1[2][4][4], acc2[2][4][4];
    ACC_INIT4(acc1);
    ACC_INIT4(acc2);

    ISSUE2(0, 0);
    ISSUE2(STG2, 128);
    uint32_t bA = 0, bB = STG2, bC = 2 * STG2;
    for (int ch = 0; ch < 4; ch++) {
        if (ch < 3) CP_WAIT1(); else CP_WAIT0();
        __syncthreads();
        if (ch < 2) ISSUE2(bC, (size_t)(ch + 2) * 128);
        mma_stage2t(sb + bA, a_off, b_off, acc1, acc2);
        uint32_t tmp = bA; bA = bB; bB = bC; bC = tmp;
    }
    ACC_COMBINE4(acc1, acc2);

    if (t < 2) {
        __half* dh = ((t == 0) ? g_qh : g_kh) + (size_t)b * NN * CC;
        __half* dm = ((t == 0) ? g_qm : g_km) + (size_t)b * NN * CC;
#pragma unroll
        for (int mi = 0; mi < 2; mi++) {
#pragma unroll
            for (int np = 0; np < 4; np++) {
                int col = wn * 32 + np * 8 + (lane & 3) * 2;
                float bc0 = bias_s[col], bc1 = bias_s[col + 1];
#pragma unroll
                for (int rh = 0; rh < 2; rh++) {
                    int row = i0 + wm * 32 + mi * 16 + rh * 8 + (lane >> 2);
                    float v0 = acc1[mi][np][rh * 2]     + bc0;
                    float v1 = acc1[mi][np][rh * 2 + 1] + bc1;
                    __half h0, m0, h1, m1;
                    f16_split2(v0, h0, m0);
                    f16_split2(v1, h1, m1);
                    union { __half e[2]; uint32_t u; } ph, pmu;
                    ph.e[0] = h0;  ph.e[1] = h1;
                    pmu.e[0] = m0; pmu.e[1] = m1;
                    *(uint32_t*)(dh + (size_t)row * CC + o0 + col) = ph.u;
                    *(uint32_t*)(dm + (size_t)row * CC + o0 + col) = pmu.u;
                }
            }
        }
    } else {
        __half* dv = g_vt + (size_t)b * CC * NN;
        float* smt = (float*)sm;   // 128 x 132 fp32
        __syncthreads();
#pragma unroll
        for (int mi = 0; mi < 2; mi++) {
            int r0 = wm * 32 + mi * 16 + (lane >> 2);
#pragma unroll
            for (int np = 0; np < 4; np++) {
                int c = wn * 32 + np * 8 + (lane & 3) * 2;
                float b0 = bias_s[c], b1 = bias_s[c + 1];
                smt[(c + 0) * 132 + r0]     = acc1[mi][np][0] + b0;
                smt[(c + 1) * 132 + r0]     = acc1[mi][np][1] + b1;
                smt[(c + 0) * 132 + r0 + 8] = acc1[mi][np][2] + b0;
                smt[(c + 1) * 132 + r0 + 8] = acc1[mi][np][3] + b1;
            }
        }
        __syncthreads();
        {
            int cl = tid >> 2, part = tid & 3;
            const float* sp = smt + cl * 132 + part * 32;
            size_t go = (size_t)(o0 + cl) * NN + i0 + part * 32;
            union { __half e[32]; uint4 v[4]; } uh;
#pragma unroll
            for (int u = 0; u < 32; u++) uh.e[u] = __float2half_rn(sp[u]);
#pragma unroll
            for (int u = 0; u < 4; u++)
                *(uint4*)(dv + go + u * 8) = uh.v[u];
        }
    }
}

// ---------------------------------------------------------------------------
// Kernel: scores, 2-term, 512 threads, tile 128x128, k-chunk 64.
// grid (32, 32, 4). Fused stats + fp16 P store. pm/pl alias stage smem.
// ---------------------------------------------------------------------------
__global__ void __launch_bounds__(512, 1) scores_mma()
{
    extern __shared__ char sm[];
    uint32_t sb = smem_u32(sm);
    int tid = threadIdx.x, wid = tid >> 5, lane = tid & 31;
    int b = blockIdx.z, i0 = blockIdx.x * 128, j0 = blockIdx.y * 128;
    int wm = wid & 3, wn = wid >> 2;

    const __half* Qh = g_qh + (size_t)b * NN * CC;
    const __half* Qm = g_qm + (size_t)b * NN * CC;
    const __half* Kh = g_kh + (size_t)b * NN * CC;
    const __half* Km = g_km + (size_t)b * NN * CC;
    __half* P = g_p + (size_t)b * NN * NN;

    int lrow = tid >> 2, lseg = (tid & 3) * 32;
    const char* gA_h = (const char*)(Qh + (size_t)(i0 + lrow) * CC) + lseg;
    const char* gA_m = (const char*)(Qm + (size_t)(i0 + lrow) * CC) + lseg;
    const char* gB_h = (const char*)(Kh + (size_t)(j0 + lrow) * CC) + lseg;
    const char* gB_m = (const char*)(Km + (size_t)(j0 + lrow) * CC) + lseg;
    uint32_t s_a = sb + lrow * RSTR + lseg;
    uint32_t s_b = sb + B2_OFF + lrow * RSTR + lseg;

    uint32_t a_off = (wm * 32 + (lane & 15)) * RSTR + ((lane >> 4) << 4);
    uint32_t b_off = (wn * 32 + (lane & 7) + ((lane >> 4) << 3)) * RSTR
                   + (((lane >> 3) & 1) << 4) + B2_OFF;

    float acc1[2][4][4], acc2[2][4][4];
    ACC_INIT4(acc1);
    ACC_INIT4(acc2);

    ISSUE2(0, 0);
    ISSUE2(STG2, 128);
    uint32_t bA = 0, bB = STG2, bC = 2 * STG2;
    for (int ch = 0; ch < 4; ch++) {
        if (ch < 3) CP_WAIT1(); else CP_WAIT0();
        __syncthreads();
        if (ch < 2) ISSUE2(bC, (size_t)(ch + 2) * 128);
        mma_stage2t(sb + bA, a_off, b_off, acc1, acc2);
        uint32_t tmp = bA; bA = bB; bB = bC; bC = tmp;
    }
    ACC_COMBINE4(acc1, acc2);

    // pm/pl alias stage smem (mainloop done; stages free)
    float* pmf = (float*)sm;           // [128][4]
    float* plf = pmf + 512;            // [128][4]
    __syncthreads();

    int q = lane >> 2, qt = lane & 3;
    float mloc[2][2];
#pragma unroll
    for (int mi = 0; mi < 2; mi++)
#pragma unroll
        for (int rh = 0; rh < 2; rh++) {
            float m = -1e30f;
#pragma unroll
            for (int np = 0; np < 4; np++)
                m = fmaxf(m, fmaxf(acc1[mi][np][rh * 2], acc1[mi][np][rh * 2 + 1]));
            mloc[mi][rh] = m;
        }
#pragma unroll
    for (int d = 1; d <= 2; d <<= 1)
#pragma unroll
        for (int mi = 0; mi < 2; mi++)
#pragma unroll
            for (int rh = 0; rh < 2; rh++)
                mloc[mi][rh] = fmaxf(mloc[mi][rh],
                                     __shfl_xor_sync(0xffffffffu, mloc[mi][rh], d));
    if (qt == 0)
#pragma unroll
        for (int mi = 0; mi < 2; mi++)
#pragma unroll
            for (int rh = 0; rh < 2; rh++)
                pmf[(wm * 32 + mi * 16 + rh * 8 + q) * 4 + wn] = mloc[mi][rh];
    __syncthreads();

    float mrow[2][2], srow[2][2];
#pragma unroll
    for (int mi = 0; mi < 2; mi++)
#pragma unroll
        for (int rh = 0; rh < 2; rh++) {
            int row = wm * 32 + mi * 16 + rh * 8 + q;
            float m = fmaxf(fmaxf(pmf[row * 4 + 0], pmf[row * 4 + 1]),
                            fmaxf(pmf[row * 4 + 2], pmf[row * 4 + 3]));
            mrow[mi][rh] = m;
            __half* prow = P + (size_t)(i0 + row) * NN + j0 + wn * 32 + qt * 2;
            float s = 0.0f;
#pragma unroll
            for (int np = 0; np < 4; np++) {
                float e0 = fast_exp(acc1[mi][np][rh * 2]     - m);
                float e1 = fast_exp(acc1[mi][np][rh * 2 + 1] - m);
                s += e0 + e1;
                *(__half2*)(prow + np * 8) = __floats2half2_rn(e0, e1);
            }
            srow[mi][rh] = s;
        }
#pragma unroll
    for (int d = 1; d <= 2; d <<= 1)
#pragma unroll
        for (int mi = 0; mi < 2; mi++)
#pragma unroll
            for (int rh = 0; rh < 2; rh++)
                srow[mi][rh] += __shfl_xor_sync(0xffffffffu, srow[mi][rh], d);
    if (qt == 0)
#pragma unroll
        for (int mi = 0; mi < 2; mi++)
#pragma unroll
            for (int rh = 0; rh < 2; rh++)
                plf[(wm * 32 + mi * 16 + rh * 8 + q) * 4 + wn] = srow[mi][rh];
    __syncthreads();
    if (qt == 0 && wn == 0)
#pragma unroll
        for (int mi = 0; mi < 2; mi++)
#pragma unroll
            for (int rh = 0; rh < 2; rh++) {
                int row = wm * 32 + mi * 16 + rh * 8 + q;
                size_t idx = ((size_t)b * NN + i0 + row) * 32 + blockIdx.y;
                g_pm[idx] = mrow[mi][rh];
                g_pl[idx] = plf[row * 4 + 0] + plf[row * 4 + 1]
                          + plf[row * 4 + 2] + plf[row * 4 + 3];
            }
}

// ---------------------------------------------------------------------------
// Kernel: merge 32 partials per row. One warp per row.
// ---------------------------------------------------------------------------
__global__ __launch_bounds__(256) void merge_kernel()
{
    int row  = blockIdx.x * 8 + (threadIdx.x >> 5);
    int lane = threadIdx.x & 31;
    float m_t = g_pm[(size_t)row * 32 + lane];
    float l_t = g_pl[(size_t)row * 32 + lane];
    float m = m_t;
#pragma unroll
    for (int d = 16; d > 0; d >>= 1) m = fmaxf(m, __shfl_xor_sync(0xffffffffu, m, d));
    float l = l_t * fast_exp(m_t - m);
#pragma unroll
    for (int d = 16; d > 0; d >>= 1) l += __shfl_xor_sync(0xffffffffu, l, d);
    if (lane == 0) { g_m[row] = m; g_li[row] = 1.0f / l; }
}

// ---------------------------------------------------------------------------
// Kernel: PV, 1-term, k-chunk 64 (64 rounds). P pre-exponentiated, rescaled
// per (row, 128-col tile). grid (32, 1, 4), 512 threads.
// ---------------------------------------------------------------------------
__global__ void __launch_bounds__(512, 1) pv_mma(float* __restrict__ out)
{
    extern __shared__ char sm[];
    __shared__ float m_s[128], li_s[128];
    __shared__ float pm_s[128][32];
    uint32_t sb = smem_u32(sm);
    int tid = threadIdx.x, wid = tid >> 5, lane = tid & 31;
    int b = blockIdx.z, i0 = blockIdx.x * 128;
    int wm = wid & 3, wn = wid >> 2;

    const __half* P = g_p + (size_t)b * NN * NN;
    const __half* V = g_vt + (size_t)b * CC * NN;

    if (tid < 128) {
        m_s[tid]  = g_m[b * NN + i0 + tid];
        li_s[tid] = g_li[b * NN + i0 + tid];
    }
#pragma unroll
    for (int idx = tid; idx < 128 * 32; idx += 512)
        pm_s[idx >> 5][idx & 31] = g_pm[((size_t)b * NN + i0 + (idx >> 5)) * 32 + (idx & 31)];

    int arow = tid >> 2, aq = tid & 3;
    const __half* gP = P + (size_t)(i0 + arow) * NN + aq * 16;
    uint32_t s_aw_off = (uint32_t)arow * RSTR + aq * 32;

    int brow = tid >> 1, bhalf = (tid & 1) * 64;
    const char* gv = (const char*)(V + (size_t)brow * NN) + bhalf;
    uint32_t s_b = sb + PB_OFF + brow * RSTR + bhalf;

    uint32_t a_off = (wm * 32 + (lane & 15)) * RSTR + ((lane >> 4) << 4);
    uint32_t b_off = (wn * 64 + (lane & 7) + ((lane >> 4) << 3)) * RSTR
                   + (((lane >> 3) & 1) << 4) + PB_OFF;

    float acc[2][8][4];
#pragma unroll
    for (int i = 0; i < 2; i++)
#pragma unroll
        for (int j = 0; j < 8; j++)
#pragma unroll
            for (int r = 0; r < 4; r++) acc[i][j][r] = 0.0f;

#define ISSUE_V(stg_base, goff) do {                              \
        uint32_t d = s_b + (stg_base);                            \
        CP16(d,      gv + (goff));                                \
        CP16(d + 16, gv + (goff) + 16);                           \
        CP16(d + 32, gv + (goff) + 32);                           \
        CP16(d + 48, gv + (goff) + 48);                           \
        CP_COMMIT();                                              \
    } while (0)

#define PRODUCE_A(stg_base, chk) do {                                       \
        float scf = fast_exp(pm_s[arow][(chk) >> 1] - mrow);                \
        __half2 sc2 = __float2half2_rn(scf);                                \
        union { __half2 h[4]; uint4 v; } u0, u1;                            \
        u0.v = sv[0]; u1.v = sv[1];                                         \
        u0.h[0] = __hmul2(u0.h[0], sc2); u0.h[1] = __hmul2(u0.h[1], sc2);   \
        u0.h[2] = __hmul2(u0.h[2], sc2); u0.h[3] = __hmul2(u0.h[3], sc2);   \
        u1.h[0] = __hmul2(u1.h[0], sc2); u1.h[1] = __hmul2(u1.h[1], sc2);   \
        u1.h[2] = __hmul2(u1.h[2], sc2); u1.h[3] = __hmul2(u1.h[3], sc2);   \
        uint32_t doff = s_aw_off + (stg_base);                              \
        *(uint4*)(sm + doff)      = u0.v;                                   \
        *(uint4*)(sm + doff + 16) = u1.v;                                   \
    } while (0)

    uint4 sv[2];
    {
        const uint4* p = (const uint4*)gP;
        sv[0] = p[0]; sv[1] = p[1];
    }
    ISSUE_V(0, 0);
    ISSUE_V(PSTG, 128);
    __syncthreads();
    float mrow = m_s[arow];
    PRODUCE_A(0, 0);
    {
        const uint4* p = (const uint4*)(gP + 64);
        sv[0] = p[0]; sv[1] = p[1];
    }

    uint32_t bA = 0, bB = PSTG, bC = 2 * PSTG;
    for (int ch = 0; ch < 64; ch++) {
        if (ch < 63) CP_WAIT1(); else CP_WAIT0();
        __syncthreads();
        if (ch < 63) PRODUCE_A(bB, ch + 1);
        if (ch < 62) {
            ISSUE_V(bC, (size_t)(ch + 2) * 128);
            const uint4* p = (const uint4*)(gP + (size_t)(ch + 2) * 64);
            sv[0] = p[0]; sv[1] = p[1];
        }
        mma_stage1(sb + bA, a_off, b_off, acc);
        uint32_t tmp = bA; bA = bB; bB = bC; bC = tmp;
    }
#undef ISSUE_V
#undef PRODUCE_A

    float* smt = (float*)sm;
#pragma unroll
    for (int h = 0; h < 2; h++) {
        __syncthreads();
        if ((wn >> 1) == h) {
#pragma unroll
            for (int mi = 0; mi < 2; mi++) {
                int r0 = wm * 32 + mi * 16 + (lane >> 2);
                float l0 = li_s[r0], l1 = li_s[r0 + 8];
#pragma unroll
                for (int np = 0; np < 8; np++) {
                    int c = (wn & 1) * 64 + np * 8 + (lane & 3) * 2;
                    smt[(c + 0) * 132 + r0]     = acc[mi][np][0] * l0;
                    smt[(c + 1) * 132 + r0]     = acc[mi][np][1] * l0;
                    smt[(c + 0) * 132 + r0 + 8] = acc[mi][np][2] * l1;
                    smt[(c + 1) * 132 + r0 + 8] = acc[mi][np][3] * l1;
                }
            }
        }
        __syncthreads();
        {
            int cl = tid >> 2, part = tid & 3;
            float* op = out + ((size_t)b * CC + h * 128 + cl) * NN + i0 + part * 32;
            const float* sp = smt + cl * 132 + part * 32;
#pragma unroll
            for (int u = 0; u < 8; u++)
                ((float4*)op)[u] = ((const float4*)sp)[u];
        }
    }
}

extern "C" void kernel_launch(void* const* d_in, const int* in_sizes, int n_in,
                              void* d_out, int out_size)
{
    const float* x1 = (const float*)d_in[0];
    const float* x2 = (const float*)d_in[1];
    const float* Wq = (const float*)d_in[2];
    const float* bq = (const float*)d_in[3];
    const float* Wk = (const float*)d_in[4];
    const float* bk = (const float*)d_in[5];
    const float* Wv = (const float*)d_in[6];
    const float* bv = (const float*)d_in[7];
    float* out = (float*)d_out;

    cudaFuncSetAttribute(proj_mma,   cudaFuncAttributeMaxDynamicSharedMemorySize, SMEM_2);
    cudaFuncSetAttribute(scores_mma, cudaFuncAttributeMaxDynamicSharedMemorySize, SMEM_2);
    cudaFuncSetAttribute(pv_mma,     cudaFuncAttributeMaxDynamicSharedMemorySize, SMEM_P);

    wsplit_kernel<<<dim3(256, 3), 256>>>(Wq, Wk, Wv, bq, bk, bv);
    xprep_kernel<<<dim3(NN / 32, CC / 32, 2 * BB), dim3(32, 8)>>>(x1, x2);
    proj_mma<<<dim3(NN / 128, CC / 128, BB * 3), 512, SMEM_2>>>();
    scores_mma<<<dim3(NN / 128, NN / 128, BB), 512, SMEM_2>>>();
    merge_kernel<<<BB * NN / 8, 256>>>();
    pv_mma<<<dim3(NN / 128, 1, BB), 512, SMEM_P>>>(out);
}

// round 17
// speedup vs baseline: 1.2556x; 1.0036x over previous
#include <cuda_runtime.h>
#include <cuda_fp16.h>
#include <cstdint>

#define BB 4
#define CC 256
#define NN 4096

#define SSPLIT 128.0f
#define INV_S  0.0078125f     // 1/128

// ---------------------------------------------------------------------------
// Scratch. 2-term operands: (h, m) with m = fp16(h + s*(v-h)), s=128.
// X = D1 + (D2-D1)/s reconstructs hi·hi + cross terms.
// ---------------------------------------------------------------------------
__device__ __half g_x1h[(size_t)BB * NN * CC];
__device__ __half g_x1m[(size_t)BB * NN * CC];
__device__ __half g_x2h[(size_t)BB * NN * CC];
__device__ __half g_x2m[(size_t)BB * NN * CC];
__device__ __half g_wh[3 * CC * CC];
__device__ __half g_wm[3 * CC * CC];
__device__ float  g_bias[3 * CC];
__device__ __half g_qh[(size_t)BB * NN * CC];
__device__ __half g_qm[(size_t)BB * NN * CC];
__device__ __half g_kh[(size_t)BB * NN * CC];
__device__ __half g_km[(size_t)BB * NN * CC];
__device__ __half g_vt[(size_t)BB * CC * NN];     // V^T fp16 [b][c][j]
__device__ __half g_p[(size_t)BB * NN * NN];      // P = exp(S - m_tile), fp16
__device__ float g_pm[(size_t)BB * NN * 32];      // per-(row, 128-col tile) max
__device__ float g_pl[(size_t)BB * NN * 32];
__device__ float g_m [BB * NN];
__device__ float g_li[BB * NN];

// ---------------------------------------------------------------------------
// PTX helpers
// ---------------------------------------------------------------------------
__device__ __forceinline__ uint32_t smem_u32(const void* p) {
    uint32_t a;
    asm("{ .reg .u64 t; cvta.to.shared.u64 t, %1; cvt.u32.u64 %0, t; }"
        : "=r"(a) : "l"(p));
    return a;
}

#define CP16(smem, gptr) \
    asm volatile("cp.async.ca.shared.global [%0], [%1], 16;" \
                 :: "r"(smem), "l"(gptr) : "memory")
#define CP_COMMIT() asm volatile("cp.async.commit_group;" ::: "memory")
#define CP_WAIT1()  asm volatile("cp.async.wait_group 1;" ::: "memory")
#define CP_WAIT0()  asm volatile("cp.async.wait_group 0;" ::: "memory")

#define LDSM4(r0, r1, r2, r3, addr) \
    asm volatile("ldmatrix.sync.aligned.m8n8.x4.shared.b16 {%0,%1,%2,%3}, [%4];" \
                 : "=r"(r0), "=r"(r1), "=r"(r2), "=r"(r3) : "r"(addr))

__device__ __forceinline__ void mma_f16(float* d, const uint32_t* a,
                                        uint32_t b0, uint32_t b1) {
    asm volatile(
        "mma.sync.aligned.m16n8k16.row.col.f32.f16.f16.f32 "
        "{%0,%1,%2,%3}, {%4,%5,%6,%7}, {%8,%9}, {%0,%1,%2,%3};"
        : "+f"(d[0]), "+f"(d[1]), "+f"(d[2]), "+f"(d[3])
        : "r"(a[0]), "r"(a[1]), "r"(a[2]), "r"(a[3]), "r"(b0), "r"(b1));
}

// k-chunk 64 fp16 = 128B data per row, padded to 144B (144 mod 128 = 16 ->
// 8 successive rows hit all 8 16B banks: conflict-free ldmatrix).
#define RSTR    144
// scores/proj stage: Ah(18432) Am(18432) Bh(18432) Bm(18432) = 73728, x3
#define A2M_D   18432
#define B2_OFF  36864
#define B2M_D   18432
#define STG2    73728
#define SMEM_2  (3 * STG2)     // 221184 (1 CTA/SM)
// pv stage: P(18432) V(256 rows: 36864) = 55296, x3
#define PB_OFF  18432
#define PSTG    55296
#define SMEM_P  (3 * PSTG)     // 165888

__device__ __forceinline__ float fast_exp(float x) {
    float y = fmaxf(x, -87.0f) * 1.4426950408889634f;
    float z = __fadd_rn(y, 12582912.0f);
    int   k = __float_as_int(z) - 0x4B400000;
    float f = __fsub_rn(y, __fsub_rn(z, 12582912.0f));
    float p =             1.33335581e-3f;
    p = fmaf(p, f, 9.61812910e-3f);
    p = fmaf(p, f, 5.55041087e-2f);
    p = fmaf(p, f, 2.40226507e-1f);
    p = fmaf(p, f, 6.93147181e-1f);
    p = fmaf(p, f, 1.0f);
    return __int_as_float(__float_as_int(p) + (k << 23));
}

__device__ __forceinline__ void f16_split2(float v, __half& h, __half& m) {
    h = __float2half_rn(v);
    float hf = __half2float(h);
    m = __float2half_rn(fmaf(SSPLIT, v - hf, hf));
}

// ---------------------------------------------------------------------------
// Prep kernels (wsplit also stages the biases: one fewer launch)
// ---------------------------------------------------------------------------
__global__ void wsplit_kernel(const float* __restrict__ Wq,
                              const float* __restrict__ Wk,
                              const float* __restrict__ Wv,
                              const float* __restrict__ bq,
                              const float* __restrict__ bk,
                              const float* __restrict__ bv)
{
    int t = blockIdx.y;
    const float* W = (t == 0) ? Wq : (t == 1) ? Wk : Wv;
    int idx = blockIdx.x * 256 + threadIdx.x;
    float v = W[idx];
    __half h, m;
    f16_split2(v, h, m);
    g_wh[t * CC * CC + idx] = h;
    g_wm[t * CC * CC + idx] = m;
    if (blockIdx.x == 0) {
        const float* bias = (t == 0) ? bq : (t == 1) ? bk : bv;
        g_bias[t * CC + threadIdx.x] = bias[threadIdx.x];
    }
}

__global__ void xprep_kernel(const float* __restrict__ x1,
                             const float* __restrict__ x2)
{
    __shared__ float tile[32][33];
    int z = blockIdx.z;
    int b = z & 3;
    const float* src = ((z < 4) ? x1 : x2) + (size_t)b * CC * NN;
    __half* dh = ((z < 4) ? g_x1h : g_x2h) + (size_t)b * NN * CC;
    __half* dm = ((z < 4) ? g_x1m : g_x2m) + (size_t)b * NN * CC;
    int i0 = blockIdx.x * 32;
    int c0 = blockIdx.y * 32;
    int tx = threadIdx.x, ty = threadIdx.y;
#pragma unroll
    for (int u = 0; u < 32; u += 8)
        tile[ty + u][tx] = src[(size_t)(c0 + ty + u) * NN + i0 + tx];
    __syncthreads();
#pragma unroll
    for (int u = 0; u < 32; u += 8) {
        float v = tile[tx][ty + u];
        __half h, m;
        f16_split2(v, h, m);
        size_t idx = (size_t)(i0 + ty + u) * CC + c0 + tx;
        dh[idx] = h;
        dm[idx] = m;
    }
}

// ---------------------------------------------------------------------------
// 2-term dual-acc warp MMA, warp tile 32x32, k-chunk 64 (kk 0..3).
// ---------------------------------------------------------------------------
__device__ __forceinline__ void mma_stage2t(uint32_t st, uint32_t a_off, uint32_t b_off,
                                            float acc1[2][4][4], float acc2[2][4][4])
{
#pragma unroll
    for (int kk = 0; kk < 4; kk++) {
        uint32_t ah[2][4], am[2][4];
#pragma unroll
        for (int mi = 0; mi < 2; mi++) {
            uint32_t ad = st + a_off + mi * (16 * RSTR) + kk * 32;
            LDSM4(ah[mi][0], ah[mi][1], ah[mi][2], ah[mi][3], ad);
            LDSM4(am[mi][0], am[mi][1], am[mi][2], am[mi][3], ad + A2M_D);
        }
#pragma unroll
        for (int ng = 0; ng < 2; ng++) {
            uint32_t bd = st + b_off + ng * (16 * RSTR) + kk * 32;
            uint32_t bh[4], bm[4];
            LDSM4(bh[0], bh[1], bh[2], bh[3], bd);
            LDSM4(bm[0], bm[1], bm[2], bm[3], bd + B2M_D);
#pragma unroll
            for (int mi = 0; mi < 2; mi++) {
                mma_f16(acc1[mi][ng * 2],     ah[mi], bh[0], bh[1]);
                mma_f16(acc1[mi][ng * 2 + 1], ah[mi], bh[2], bh[3]);
                mma_f16(acc2[mi][ng * 2],     am[mi], bm[0], bm[1]);
                mma_f16(acc2[mi][ng * 2 + 1], am[mi], bm[2], bm[3]);
            }
        }
    }
}

// 1-term PV: warp tile 32x64, k-chunk 64.
__device__ __forceinline__ void mma_stage1(uint32_t st, uint32_t a_off, uint32_t b_off,
                                           float acc[2][8][4])
{
#pragma unroll
    for (int kk = 0; kk < 4; kk++) {
        uint32_t ah[2][4];
#pragma unroll
        for (int mi = 0; mi < 2; mi++) {
            uint32_t ad = st + a_off + mi * (16 * RSTR) + kk * 32;
            LDSM4(ah[mi][0], ah[mi][1], ah[mi][2], ah[mi][3], ad);
        }
#pragma unroll
        for (int ng = 0; ng < 4; ng++) {
            uint32_t bd = st + b_off + ng * (16 * RSTR) + kk * 32;
            uint32_t bh[4];
            LDSM4(bh[0], bh[1], bh[2], bh[3], bd);
#pragma unroll
            for (int mi = 0; mi < 2; mi++) {
                mma_f16(acc[mi][ng * 2],     ah[mi], bh[0], bh[1]);
                mma_f16(acc[mi][ng * 2 + 1], ah[mi], bh[2], bh[3]);
            }
        }
    }
}

// Loader (2-term, 512 threads, 128-row tiles of 128B data):
// thread -> (row = tid>>2, seg = (tid&3)*32); 2 CP16 per array.
#define ISSUE2(stg_base, goff) do {                               \
        uint32_t dA = s_a + (stg_base);                           \
        uint32_t dB = s_b + (stg_base);                           \
        CP16(dA,              gA_h + (goff));                     \
        CP16(dA + 16,         gA_h + (goff) + 16);                \
        CP16(dA + A2M_D,      gA_m + (goff));                     \
        CP16(dA + A2M_D + 16, gA_m + (goff) + 16);                \
        CP16(dB,              gB_h + (goff));                     \
        CP16(dB + 16,         gB_h + (goff) + 16);                \
        CP16(dB + B2M_D,      gB_m + (goff));                     \
        CP16(dB + B2M_D + 16, gB_m + (goff) + 16);                \
        CP_COMMIT();                                              \
    } while (0)

#define ACC_INIT4(a) do {                                         \
    _Pragma("unroll") for (int i = 0; i < 2; i++)                 \
    _Pragma("unroll") for (int j = 0; j < 4; j++)                 \
    _Pragma("unroll") for (int r = 0; r < 4; r++) (a)[i][j][r] = 0.0f; \
} while (0)

#define ACC_COMBINE4(a1, a2) do {                                 \
    _Pragma("unroll") for (int i = 0; i < 2; i++)                 \
    _Pragma("unroll") for (int j = 0; j < 4; j++)                 \
    _Pragma("unroll") for (int r = 0; r < 4; r++)                 \
        (a1)[i][j][r] = fmaf((a2)[i][j][r] - (a1)[i][j][r], INV_S, (a1)[i][j][r]); \
} while (0)

// ---------------------------------------------------------------------------
// Kernel: QKV projection, 2-term, 512 threads, tile 128x128, k-chunk 64.
// grid (32, 2, 12). t<2: write Q/K (h,m). t==2: transpose -> V^T fp16.
// ---------------------------------------------------------------------------
__global__ void __launch_bounds__(512, 1) proj_mma()
{
    extern __shared__ char sm[];
    __shared__ float bias_s[128];
    uint32_t sb = smem_u32(sm);
    int tid = threadIdx.x, wid = tid >> 5, lane = tid & 31;
    int z = blockIdx.z;
    int b = z / 3, t = z % 3;
    int i0 = blockIdx.x * 128;
    int o0 = blockIdx.y * 128;
    int wm = wid & 3, wn = wid >> 2;

    const __half* Xh = ((t == 0) ? g_x1h : g_x2h) + (size_t)b * NN * CC;
    const __half* Xm = ((t == 0) ? g_x1m : g_x2m) + (size_t)b * NN * CC;
    const __half* Wh = g_wh + t * CC * CC;
    const __half* Wm = g_wm + t * CC * CC;

    if (tid < 128) bias_s[tid] = g_bias[t * CC + o0 + tid];

    int lrow = tid >> 2, lseg = (tid & 3) * 32;
    const char* gA_h = (const char*)(Xh + (size_t)(i0 + lrow) * CC) + lseg;
    const char* gA_m = (const char*)(Xm + (size_t)(i0 + lrow) * CC) + lseg;
    const char* gB_h = (const char*)(Wh + (size_t)(o0 + lrow) * CC) + lseg;
    const char* gB_m = (const char*)(Wm + (size_t)(o0 + lrow) * CC) + lseg;
    uint32_t s_a = sb + lrow * RSTR + lseg;
    uint32_t s_b = sb + B2_OFF + lrow * RSTR + lseg;

    uint32_t a_off = (wm * 32 + (lane & 15)) * RSTR + ((lane >> 4) << 4);
    uint32_t b_off = (wn * 32 + (lane & 7) + ((lane >> 4) << 3)) * RSTR
                   + (((lane >> 3) & 1) << 4) + B2_OFF;

    float acc1[2][4][4], acc2[2][4][4];
    ACC_INIT4(acc1);
    ACC_INIT4(acc2);

    ISSUE2(0, 0);
    ISSUE2(STG2, 128);
    uint32_t bA = 0, bB = STG2, bC = 2 * STG2;
    for (int ch = 0; ch < 4; ch++) {
        if (ch < 3) CP_WAIT1(); else CP_WAIT0();
        __syncthreads();
        if (ch < 2) ISSUE2(bC, (size_t)(ch + 2) * 128);
        mma_stage2t(sb + bA, a_off, b_off, acc1, acc2);
        uint32_t tmp = bA; bA = bB; bB = bC; bC = tmp;
    }
    ACC_COMBINE4(acc1, acc2);

    if (t < 2) {
        __half* dh = ((t == 0) ? g_qh : g_kh) + (size_t)b * NN * CC;
        __half* dm = ((t == 0) ? g_qm : g_km) + (size_t)b * NN * CC;
#pragma unroll
        for (int mi = 0; mi < 2; mi++) {
#pragma unroll
            for (int np = 0; np < 4; np++) {
                int col = wn * 32 + np * 8 + (lane & 3) * 2;
                float bc0 = bias_s[col], bc1 = bias_s[col + 1];
#pragma unroll
                for (int rh = 0; rh < 2; rh++) {
                    int row = i0 + wm * 32 + mi * 16 + rh * 8 + (lane >> 2);
                    float v0 = acc1[mi][np][rh * 2]     + bc0;
                    float v1 = acc1[mi][np][rh * 2 + 1] + bc1;
                    __half h0, m0, h1, m1;
                    f16_split2(v0, h0, m0);
                    f16_split2(v1, h1, m1);
                    union { __half e[2]; uint32_t u; } ph, pmu;
                    ph.e[0] = h0;  ph.e[1] = h1;
                    pmu.e[0] = m0; pmu.e[1] = m1;
                    *(uint32_t*)(dh + (size_t)row * CC + o0 + col) = ph.u;
                    *(uint32_t*)(dm + (size_t)row * CC + o0 + col) = pmu.u;
                }
            }
        }
    } else {
        __half* dv = g_vt + (size_t)b * CC * NN;
        float* smt = (float*)sm;   // 128 x 132 fp32
        __syncthreads();
#pragma unroll
        for (int mi = 0; mi < 2; mi++) {
            int r0 = wm * 32 + mi * 16 + (lane >> 2);
#pragma unroll
            for (int np = 0; np < 4; np++) {
                int c = wn * 32 + np * 8 + (lane & 3) * 2;
                float b0 = bias_s[c], b1 = bias_s[c + 1];
                smt[(c + 0) * 132 + r0]     = acc1[mi][np][0] + b0;
                smt[(c + 1) * 132 + r0]     = acc1[mi][np][1] + b1;
                smt[(c + 0) * 132 + r0 + 8] = acc1[mi][np][2] + b0;
                smt[(c + 1) * 132 + r0 + 8] = acc1[mi][np][3] + b1;
            }
        }
        __syncthreads();
        {
            int cl = tid >> 2, part = tid & 3;
            const float* sp = smt + cl * 132 + part * 32;
            size_t go = (size_t)(o0 + cl) * NN + i0 + part * 32;
            union { __half e[32]; uint4 v[4]; } uh;
#pragma unroll
            for (int u = 0; u < 32; u++) uh.e[u] = __float2half_rn(sp[u]);
#pragma unroll
            for (int u = 0; u < 4; u++)
                *(uint4*)(dv + go + u * 8) = uh.v[u];
        }
    }
}

// ---------------------------------------------------------------------------
// Kernel: scores, 2-term, 512 threads, tile 128x128, k-chunk 64.
// grid (32, 32, 4). Fused stats + fp16 P store. pm/pl alias stage smem.
// ---------------------------------------------------------------------------
__global__ void __launch_bounds__(512, 1) scores_mma()
{
    extern __shared__ char sm[];
    uint32_t sb = smem_u32(sm);
    int tid = threadIdx.x, wid = tid >> 5, lane = tid & 31;
    int b = blockIdx.z, i0 = blockIdx.x * 128, j0 = blockIdx.y * 128;
    int wm = wid & 3, wn = wid >> 2;

    const __half* Qh = g_qh + (size_t)b * NN * CC;
    const __half* Qm = g_qm + (size_t)b * NN * CC;
    const __half* Kh = g_kh + (size_t)b * NN * CC;
    const __half* Km = g_km + (size_t)b * NN * CC;
    __half* P = g_p + (size_t)b * NN * NN;

    int lrow = tid >> 2, lseg = (tid & 3) * 32;
    const char* gA_h = (const char*)(Qh + (size_t)(i0 + lrow) * CC) + lseg;
    const char* gA_m = (const char*)(Qm + (size_t)(i0 + lrow) * CC) + lseg;
    const char* gB_h = (const char*)(Kh + (size_t)(j0 + lrow) * CC) + lseg;
    const char* gB_m = (const char*)(Km + (size_t)(j0 + lrow) * CC) + lseg;
    uint32_t s_a = sb + lrow * RSTR + lseg;
    uint32_t s_b = sb + B2_OFF + lrow * RSTR + lseg;

    uint32_t a_off = (wm * 32 + (lane & 15)) * RSTR + ((lane >> 4) << 4);
    uint32_t b_off = (wn * 32 + (lane & 7) + ((lane >> 4) << 3)) * RSTR
                   + (((lane >> 3) & 1) << 4) + B2_OFF;

    float acc1[2][4][4], acc2[2][4][4];
    ACC_INIT4(acc1);
    ACC_INIT4(acc2);

    ISSUE2(0, 0);
    ISSUE2(STG2, 128);
    uint32_t bA = 0, bB = STG2, bC = 2 * STG2;
    for (int ch = 0; ch < 4; ch++) {
        if (ch < 3) CP_WAIT1(); else CP_WAIT0();
        __syncthreads();
        if (ch < 2) ISSUE2(bC, (size_t)(ch + 2) * 128);
        mma_stage2t(sb + bA, a_off, b_off, acc1, acc2);
        uint32_t tmp = bA; bA = bB; bB = bC; bC = tmp;
    }
    ACC_COMBINE4(acc1, acc2);

    // pm/pl alias stage smem (mainloop done; stages free)
    float* pmf = (float*)sm;           // [128][4]
    float* plf = pmf + 512;            // [128][4]
    __syncthreads();

    int q = lane >> 2, qt = lane & 3;
    float mloc[2][2];
#pragma unroll
    for (int mi = 0; mi < 2; mi++)
#pragma unroll
        for (int rh = 0; rh < 2; rh++) {
            float m = -1e30f;
#pragma unroll
            for (int np = 0; np < 4; np++)
                m = fmaxf(m, fmaxf(acc1[mi][np][rh * 2], acc1[mi][np][rh * 2 + 1]));
            mloc[mi][rh] = m;
        }
#pragma unroll
    for (int d = 1; d <= 2; d <<= 1)
#pragma unroll
        for (int mi = 0; mi < 2; mi++)
#pragma unroll
            for (int rh = 0; rh < 2; rh++)
                mloc[mi][rh] = fmaxf(mloc[mi][rh],
                                     __shfl_xor_sync(0xffffffffu, mloc[mi][rh], d));
    if (qt == 0)
#pragma unroll
        for (int mi = 0; mi < 2; mi++)
#pragma unroll
            for (int rh = 0; rh < 2; rh++)
                pmf[(wm * 32 + mi * 16 + rh * 8 + q) * 4 + wn] = mloc[mi][rh];
    __syncthreads();

    float mrow[2][2], srow[2][2];
#pragma unroll
    for (int mi = 0; mi < 2; mi++)
#pragma unroll
        for (int rh = 0; rh < 2; rh++) {
            int row = wm * 32 + mi * 16 + rh * 8 + q;
            float m = fmaxf(fmaxf(pmf[row * 4 + 0], pmf[row * 4 + 1]),
                            fmaxf(pmf[row * 4 + 2], pmf[row * 4 + 3]));
            mrow[mi][rh] = m;
            __half* prow = P + (size_t)(i0 + row) * NN + j0 + wn * 32 + qt * 2;
            float s = 0.0f;
#pragma unroll
            for (int np = 0; np < 4; np++) {
                float e0 = fast_exp(acc1[mi][np][rh * 2]     - m);
                float e1 = fast_exp(acc1[mi][np][rh * 2 + 1] - m);
                s += e0 + e1;
                *(__half2*)(prow + np * 8) = __floats2half2_rn(e0, e1);
            }
            srow[mi][rh] = s;
        }
#pragma unroll
    for (int d = 1; d <= 2; d <<= 1)
#pragma unroll
        for (int mi = 0; mi < 2; mi++)
#pragma unroll
            for (int rh = 0; rh < 2; rh++)
                srow[mi][rh] += __shfl_xor_sync(0xffffffffu, srow[mi][rh], d);
    if (qt == 0)
#pragma unroll
        for (int mi = 0; mi < 2; mi++)
#pragma unroll
            for (int rh = 0; rh < 2; rh++)
                plf[(wm * 32 + mi * 16 + rh * 8 + q) * 4 + wn] = srow[mi][rh];
    __syncthreads();
    if (qt == 0 && wn == 0)
#pragma unroll
        for (int mi = 0; mi < 2; mi++)
#pragma unroll
            for (int rh = 0; rh < 2; rh++) {
                int row = wm * 32 + mi * 16 + rh * 8 + q;
                size_t idx = ((size_t)b * NN + i0 + row) * 32 + blockIdx.y;
                g_pm[idx] = mrow[mi][rh];
                g_pl[idx] = plf[row * 4 + 0] + plf[row * 4 + 1]
                          + plf[row * 4 + 2] + plf[row * 4 + 3];
            }
}

// ---------------------------------------------------------------------------
// Kernel: merge 32 partials per row. One warp per row.
// ---------------------------------------------------------------------------
__global__ __launch_bounds__(256) void merge_kernel()
{
    int row  = blockIdx.x * 8 + (threadIdx.x >> 5);
    int lane = threadIdx.x & 31;
    float m_t = g_pm[(size_t)row * 32 + lane];
    float l_t = g_pl[(size_t)row * 32 + lane];
    float m = m_t;
#pragma unroll
    for (int d = 16; d > 0; d >>= 1) m = fmaxf(m, __shfl_xor_sync(0xffffffffu, m, d));
    float l = l_t * fast_exp(m_t - m);
#pragma unroll
    for (int d = 16; d > 0; d >>= 1) l += __shfl_xor_sync(0xffffffffu, l, d);
    if (lane == 0) { g_m[row] = m; g_li[row] = 1.0f / l; }
}

// ---------------------------------------------------------------------------
// Kernel: PV, 1-term, k-chunk 64 (64 rounds). P pre-exponentiated, rescaled
// per (row, 128-col tile). grid (32, 1, 4), 512 threads.
// ---------------------------------------------------------------------------
__global__ void __launch_bounds__(512, 1) pv_mma(float* __restrict__ out)
{
    extern __shared__ char sm[];
    __shared__ float m_s[128], li_s[128];
    __shared__ float pm_s[128][32];
    uint32_t sb = smem_u32(sm);
    int tid = threadIdx.x, wid = tid >> 5, lane = tid & 31;
    int b = blockIdx.z, i0 = blockIdx.x * 128;
    int wm = wid & 3, wn = wid >> 2;

    const __half* P = g_p + (size_t)b * NN * NN;
    const __half* V = g_vt + (size_t)b * CC * NN;

    if (tid < 128) {
        m_s[tid]  = g_m[b * NN + i0 + tid];
        li_s[tid] = g_li[b * NN + i0 + tid];
    }
#pragma unroll
    for (int idx = tid; idx < 128 * 32; idx += 512)
        pm_s[idx >> 5][idx & 31] = g_pm[((size_t)b * NN + i0 + (idx >> 5)) * 32 + (idx & 31)];

    int arow = tid >> 2, aq = tid & 3;
    const __half* gP = P + (size_t)(i0 + arow) * NN + aq * 16;
    uint32_t s_aw_off = (uint32_t)arow * RSTR + aq * 32;

    int brow = tid >> 1, bhalf = (tid & 1) * 64;
    const char* gv = (const char*)(V + (size_t)brow * NN) + bhalf;
    uint32_t s_b = sb + PB_OFF + brow * RSTR + bhalf;

    uint32_t a_off = (wm * 32 + (lane & 15)) * RSTR + ((lane >> 4) << 4);
    uint32_t b_off = (wn * 64 + (lane & 7) + ((lane >> 4) << 3)) * RSTR
                   + (((lane >> 3) & 1) << 4) + PB_OFF;

    float acc[2][8][4];
#pragma unroll
    for (int i = 0; i < 2; i++)
#pragma unroll
        for (int j = 0; j < 8; j++)
#pragma unroll
            for (int r = 0; r < 4; r++) acc[i][j][r] = 0.0f;

#define ISSUE_V(stg_base, goff) do {                              \
        uint32_t d = s_b + (stg_base);                            \
        CP16(d,      gv + (goff));                                \
        CP16(d + 16, gv + (goff) + 16);                           \
        CP16(d + 32, gv + (goff) + 32);                           \
        CP16(d + 48, gv + (goff) + 48);                           \
        CP_COMMIT();                                              \
    } while (0)

#define PRODUCE_A(stg_base, chk) do {                                       \
        float scf = fast_exp(pm_s[arow][(chk) >> 1] - mrow);                \
        __half2 sc2 = __float2half2_rn(scf);                                \
        union { __half2 h[4]; uint4 v; } u0, u1;                            \
        u0.v = sv[0]; u1.v = sv[1];                                         \
        u0.h[0] = __hmul2(u0.h[0], sc2); u0.h[1] = __hmul2(u0.h[1], sc2);   \
        u0.h[2] = __hmul2(u0.h[2], sc2); u0.h[3] = __hmul2(u0.h[3], sc2);   \
        u1.h[0] = __hmul2(u1.h[0], sc2); u1.h[1] = __hmul2(u1.h[1], sc2);   \
        u1.h[2] = __hmul2(u1.h[2], sc2); u1.h[3] = __hmul2(u1.h[3], sc2);   \
        uint32_t doff = s_aw_off + (stg_base);                              \
        *(uint4*)(sm + doff)      = u0.v;                                   \
        *(uint4*)(sm + doff + 16) = u1.v;                                   \
    } while (0)

    uint4 sv[2];
    {
        const uint4* p = (const uint4*)gP;
        sv[0] = p[0]; sv[1] = p[1];
    }
    ISSUE_V(0, 0);
    ISSUE_V(PSTG, 128);
    __syncthreads();
    float mrow = m_s[arow];
    PRODUCE_A(0, 0);
    {
        const uint4* p = (const uint4*)(gP + 64);
        sv[0] = p[0]; sv[1] = p[1];
    }

    uint32_t bA = 0, bB = PSTG, bC = 2 * PSTG;
    for (int ch = 0; ch < 64; ch++) {
        if (ch < 63) CP_WAIT1(); else CP_WAIT0();
        __syncthreads();
        if (ch < 63) PRODUCE_A(bB, ch + 1);
        if (ch < 62) {
            ISSUE_V(bC, (size_t)(ch + 2) * 128);
            const uint4* p = (const uint4*)(gP + (size_t)(ch + 2) * 64);
            sv[0] = p[0]; sv[1] = p[1];
        }
        mma_stage1(sb + bA, a_off, b_off, acc);
        uint32_t tmp = bA; bA = bB; bB = bC; bC = tmp;
    }
#undef ISSUE_V
#undef PRODUCE_A

    float* smt = (float*)sm;
#pragma unroll
    for (int h = 0; h < 2; h++) {
        __syncthreads();
        if ((wn >> 1) == h) {
#pragma unroll
            for (int mi = 0; mi < 2; mi++) {
                int r0 = wm * 32 + mi * 16 + (lane >> 2);
                float l0 = li_s[r0], l1 = li_s[r0 + 8];
#pragma unroll
                for (int np = 0; np < 8; np++) {
                    int c = (wn & 1) * 64 + np * 8 + (lane & 3) * 2;
                    smt[(c + 0) * 132 + r0]     = acc[mi][np][0] * l0;
                    smt[(c + 1) * 132 + r0]     = acc[mi][np][1] * l0;
                    smt[(c + 0) * 132 + r0 + 8] = acc[mi][np][2] * l1;
                    smt[(c + 1) * 132 + r0 + 8] = acc[mi][np][3] * l1;
                }
            }
        }
        __syncthreads();
        {
            int cl = tid >> 2, part = tid & 3;
            float* op = out + ((size_t)b * CC + h * 128 + cl) * NN + i0 + part * 32;
            const float* sp = smt + cl * 132 + part * 32;
#pragma unroll
            for (int u = 0; u < 8; u++)
                ((float4*)op)[u] = ((const float4*)sp)[u];
        }
    }
}

extern "C" void kernel_launch(void* const* d_in, const int* in_sizes, int n_in,
                              void* d_out, int out_size)
{
    const float* x1 = (const float*)d_in[0];
    const float* x2 = (const float*)d_in[1];
    const float* Wq = (const float*)d_in[2];
    const float* bq = (const float*)d_in[3];
    const float* Wk = (const float*)d_in[4];
    const float* bk = (const float*)d_in[5];
    const float* Wv = (const float*)d_in[6];
    const float* bv = (const float*)d_in[7];
    float* out = (float*)d_out;

    cudaFuncSetAttribute(proj_mma,   cudaFuncAttributeMaxDynamicSharedMemorySize, SMEM_2);
    cudaFuncSetAttribute(scores_mma, cudaFuncAttributeMaxDynamicSharedMemorySize, SMEM_2);
    cudaFuncSetAttribute(pv_mma,     cudaFuncAttributeMaxDynamicSharedMemorySize, SMEM_P);

    wsplit_kernel<<<dim3(256, 3), 256>>>(Wq, Wk, Wv, bq, bk, bv);
    xprep_kernel<<<dim3(NN / 32, CC / 32, 2 * BB), dim3(32, 8)>>>(x1, x2);
    proj_mma<<<dim3(NN / 128, CC / 128, BB * 3), 512, SMEM_2>>>();
    scores_mma<<<dim3(NN / 128, NN / 128, BB), 512, SMEM_2>>>();
    merge_kernel<<<BB * NN / 8, 256>>>();
    pv_mma<<<dim3(NN / 128, 1, BB), 512, SMEM_P>>>(out);
}